// round 8
// baseline (speedup 1.0000x reference)
#include <cuda_runtime.h>
#include <cuda_bf16.h>
#include <cstdint>

#define IN_F   4096
#define OUT_F  768
#define BITS   6144
#define BATCH  1024

#define BM 64
#define BN 64
#define BKK 64
#define PAD 72                 // padded row length (u16 elems)
#define NKC (IN_F / BKK)       // 64
#define NSTAGE 3
#define GX (OUT_F / BN)        // 12
#define GY (BATCH / BM)        // 16
#define NCTA (GX * GY)         // 192
#define ST_ELEMS (BM * PAD)    // 4608 u16 per operand per stage
#define DSMEM_BYTES (NSTAGE * ST_ELEMS * 2 * 2)   // 55296

// ---------------- device scratch ----------------
__device__ __nv_bfloat16 g_wT[(size_t)OUT_F * IN_F];
__device__ __nv_bfloat16 g_lat[(size_t)BATCH * IN_F];
__device__ float g_reg_part[3072];
__device__ float g_recon_part[NCTA];
__device__ int   g_ticket;

// ---------------- helpers ----------------
__device__ __forceinline__ float tanh_fast(float x) {
    float y; asm("tanh.approx.f32 %0, %1;" : "=f"(y) : "f"(x)); return y;
}
__device__ __forceinline__ uint32_t cvta_s(const void* p) {
    return (uint32_t)__cvta_generic_to_shared(p);
}
#define CP_ASYNC16(s, g) asm volatile("cp.async.cg.shared.global [%0], [%1], 16;\n" :: "r"(s), "l"(g))
#define CP_COMMIT        asm volatile("cp.async.commit_group;\n" ::: "memory")
#define CP_WAIT0         asm volatile("cp.async.wait_group 0;\n" ::: "memory")
#define CP_WAIT1         asm volatile("cp.async.wait_group 1;\n" ::: "memory")
// NOTE: non-volatile MMA — outputs keep it live; scheduler may software-pipeline
#define MMA(d, a0, a1, a2, a3, b0, b1) \
    asm("mma.sync.aligned.m16n8k16.row.col.f32.bf16.bf16.f32 " \
        "{%0,%1,%2,%3},{%4,%5,%6,%7},{%8,%9},{%0,%1,%2,%3};\n" \
        : "+f"(d[0]), "+f"(d[1]), "+f"(d[2]), "+f"(d[3]) \
        : "r"(a0), "r"(a1), "r"(a2), "r"(a3), "r"(b0), "r"(b1))

// ---------------- fused pre-pass ----------------
__global__ void k_pre(const float* __restrict__ w, const float* __restrict__ lat) {
    int bx = blockIdx.x;
    int t = threadIdx.x;

    if (bx < 3072) {
        __shared__ float s_iw[32][33];
        __shared__ float s_red[8];
        const float pwh[8] = {0.5f, 1.f, 2.f, 4.f, 8.f, 16.f, 32.f, -64.f};

        int k0 = (bx & 127) * 32;
        int n0 = (bx >> 7) * 32;

        float regloc = 0.f;
#pragma unroll
        for (int i = 0; i < 4; i++) {
            int c = t + i * 256;
            int kk = c >> 5, nn = c & 31;
            const float4* p = reinterpret_cast<const float4*>(
                w + (size_t)(k0 + kk) * BITS + (size_t)(n0 + nn) * 8);
            float4 w0 = p[0], w1 = p[1];
            float xs[8] = {w0.x, w0.y, w0.z, w0.w, w1.x, w1.y, w1.z, w1.w};
            float iwt = 0.f, sab = 0.f;
#pragma unroll
            for (int b = 0; b < 8; b++) {
                float th = tanh_fast(0.5f * xs[b]);
                iwt = fmaf(th, pwh[b], iwt);
                sab += fabsf(th);
            }
            s_iw[kk][nn] = iwt - 0.5f;
            regloc += fmaf(-0.5f, sab, 4.0f);
        }
        __syncthreads();
#pragma unroll
        for (int i = 0; i < 4; i++) {
            int c = t + i * 256;
            int nn = c >> 5, kk = c & 31;
            g_wT[(size_t)(n0 + nn) * IN_F + (k0 + kk)] = __float2bfloat16(s_iw[kk][nn]);
        }
#pragma unroll
        for (int o = 16; o > 0; o >>= 1)
            regloc += __shfl_xor_sync(0xffffffffu, regloc, o);
        if ((t & 31) == 0) s_red[t >> 5] = regloc;
        __syncthreads();
        if (t == 0) {
            float s = 0.f;
#pragma unroll
            for (int i = 0; i < 8; i++) s += s_red[i];
            g_reg_part[bx] = s;
        }
    } else {
        int i = (bx - 3072) * 256 + t;
        const int stride = 1024 * 256;
        const float4* src = reinterpret_cast<const float4*>(lat);
        __nv_bfloat162* o = reinterpret_cast<__nv_bfloat162*>(g_lat);
        float4 v[4];
#pragma unroll
        for (int j = 0; j < 4; j++) v[j] = src[i + j * stride];
#pragma unroll
        for (int j = 0; j < 4; j++) {
            int idx = i + j * stride;
            o[2 * idx]     = __floats2bfloat162_rn(v[j].x, v[j].y);
            o[2 * idx + 1] = __floats2bfloat162_rn(v[j].z, v[j].w);
        }
    }
}

// int_sum(r,n)/255 from true_sum
__device__ __forceinline__ float tval(const float* __restrict__ ts, int r, int n) {
    const float4* p = reinterpret_cast<const float4*>(ts + ((size_t)r * OUT_F + n) * 8);
    float4 a = p[0], b = p[1];
    return (a.x + 2.f * a.y + 4.f * a.z + 8.f * a.w
            + 16.f * b.x + 32.f * b.y + 64.f * b.z - 128.f * b.w) * (1.0f / 255.0f);
}

// stage loader: 512 16B vectors per operand, 2 per thread each
__device__ __forceinline__ void load_tile(
    uint16_t* Asb, uint16_t* Bsb,
    const __nv_bfloat16* gA, const __nv_bfloat16* gB, int kbase, int t)
{
#pragma unroll
    for (int j = 0; j < 2; j++) {
        int id = t + j * 256;
        int row = id >> 3, c = id & 7;
        CP_ASYNC16(cvta_s(&Asb[row * PAD + c * 8]),
                   gA + (size_t)row * IN_F + kbase + c * 8);
        CP_ASYNC16(cvta_s(&Bsb[row * PAD + c * 8]),
                   gB + (size_t)row * IN_F + kbase + c * 8);
    }
}

// GEMM 64x64 tiles, 192 CTAs, 3-stage cp.async, C++ fragment loads (compiler-pipelined)
__global__ void __launch_bounds__(256, 2)
k_gemm_loss(const float* __restrict__ ts, float* __restrict__ out, int out_size) {
    extern __shared__ __align__(16) uint8_t dsm[];
    uint16_t* As = (uint16_t*)dsm;             // NSTAGE * ST_ELEMS
    uint16_t* Bs = As + NSTAGE * ST_ELEMS;

    __shared__ float s_red[8], s_red2[8];
    __shared__ int s_last;

    int n0 = blockIdx.x * BN;
    int m0 = blockIdx.y * BM;
    int t = threadIdx.x;
    int wid = t >> 5, lane = t & 31;
    int wm = wid & 1, wn = wid >> 1;           // warp tile 32x16
    int gid = lane >> 2, tig = lane & 3;

    const __nv_bfloat16* gA = g_lat + (size_t)m0 * IN_F;
    const __nv_bfloat16* gB = g_wT + (size_t)n0 * IN_F;

    float acc[2][2][4] = {};

    // fragment base rows
    int rA0 = wm * 32 + gid;                   // + mt*16, +8
    int rB0 = wn * 16 + gid;                   // + nt*8

    // prologue: stages 0,1
    load_tile(As, Bs, gA, gB, 0, t); CP_COMMIT;
    load_tile(As + ST_ELEMS, Bs + ST_ELEMS, gA, gB, BKK, t); CP_COMMIT;

    int buf = 0;
    for (int kc = 0; kc < NKC; kc++) {
        if (kc + 1 < NKC) { CP_WAIT1; } else { CP_WAIT0; }
        __syncthreads();

        if (kc + 2 < NKC) {
            int b2 = buf + 2; if (b2 >= NSTAGE) b2 -= NSTAGE;
            load_tile(As + b2 * ST_ELEMS, Bs + b2 * ST_ELEMS, gA, gB, (kc + 2) * BKK, t);
            CP_COMMIT;
        }

        const uint16_t* Ab = As + buf * ST_ELEMS;
        const uint16_t* Bb = Bs + buf * ST_ELEMS;

#pragma unroll
        for (int s = 0; s < 4; s++) {          // k16 steps
            int ks = s * 16 + tig * 2;
            uint32_t af[2][4], bf[2][2];
#pragma unroll
            for (int mt = 0; mt < 2; mt++) {
                int r = rA0 + mt * 16;
                af[mt][0] = *reinterpret_cast<const uint32_t*>(&Ab[r * PAD + ks]);
                af[mt][1] = *reinterpret_cast<const uint32_t*>(&Ab[(r + 8) * PAD + ks]);
                af[mt][2] = *reinterpret_cast<const uint32_t*>(&Ab[r * PAD + ks + 8]);
                af[mt][3] = *reinterpret_cast<const uint32_t*>(&Ab[(r + 8) * PAD + ks + 8]);
            }
#pragma unroll
            for (int nt = 0; nt < 2; nt++) {
                int r = rB0 + nt * 8;
                bf[nt][0] = *reinterpret_cast<const uint32_t*>(&Bb[r * PAD + ks]);
                bf[nt][1] = *reinterpret_cast<const uint32_t*>(&Bb[r * PAD + ks + 8]);
            }
#pragma unroll
            for (int mt = 0; mt < 2; mt++)
#pragma unroll
                for (int nt = 0; nt < 2; nt++)
                    MMA(acc[mt][nt], af[mt][0], af[mt][1], af[mt][2], af[mt][3],
                        bf[nt][0], bf[nt][1]);
        }
        buf++; if (buf >= NSTAGE) buf = 0;
    }

    // fused loss
    float lsum = 0.f;
#pragma unroll
    for (int mt = 0; mt < 2; mt++)
#pragma unroll
        for (int nt = 0; nt < 2; nt++) {
            int r  = m0 + wm * 32 + mt * 16 + gid;
            int nc = n0 + wn * 16 + nt * 8 + tig * 2;
            float e0 = fmaf(acc[mt][nt][0], 1.f / 255.f, -tval(ts, r,     nc));
            float e1 = fmaf(acc[mt][nt][1], 1.f / 255.f, -tval(ts, r,     nc + 1));
            float e2 = fmaf(acc[mt][nt][2], 1.f / 255.f, -tval(ts, r + 8, nc));
            float e3 = fmaf(acc[mt][nt][3], 1.f / 255.f, -tval(ts, r + 8, nc + 1));
            lsum += e0 * e0 + e1 * e1 + e2 * e2 + e3 * e3;
        }
#pragma unroll
    for (int o = 16; o > 0; o >>= 1)
        lsum += __shfl_xor_sync(0xffffffffu, lsum, o);
    if (lane == 0) s_red[wid] = lsum;
    __syncthreads();

    if (t == 0) {
        float s = 0.f;
#pragma unroll
        for (int i = 0; i < 8; i++) s += s_red[i];
        g_recon_part[blockIdx.y * GX + blockIdx.x] = s;
        __threadfence();
        int old = atomicAdd(&g_ticket, 1);
        s_last = (old == NCTA - 1) ? 1 : 0;
    }
    __syncthreads();

    if (s_last) {
        float rr = 0.f, ss = 0.f;
        for (int i = t; i < 3072; i += 256) rr += __ldcg(&g_reg_part[i]);
        if (t < NCTA) ss = __ldcg(&g_recon_part[t]);
#pragma unroll
        for (int o = 16; o > 0; o >>= 1) {
            rr += __shfl_xor_sync(0xffffffffu, rr, o);
            ss += __shfl_xor_sync(0xffffffffu, ss, o);
        }
        if ((t & 31) == 0) { s_red[t >> 5] = rr; s_red2[t >> 5] = ss; }
        __syncthreads();
        if (t == 0) {
            float R = 0.f, S = 0.f;
#pragma unroll
            for (int i = 0; i < 8; i++) { R += s_red[i]; S += s_red2[i]; }
            float recon = S * (1.0f / ((float)BATCH * OUT_F));
            float reg   = 0.001f * R * (1.0f / ((float)IN_F * (float)BITS));
            if (out_size > 0) out[0] = recon + reg;
            if (out_size > 1) out[1] = recon;
            if (out_size > 2) out[2] = reg;
            g_ticket = 0;
        }
    }
}

// ---------------- launch ----------------
extern "C" void kernel_launch(void* const* d_in, const int* in_sizes, int n_in,
                              void* d_out, int out_size) {
    const float* latent   = (const float*)d_in[0];
    const float* true_sum = (const float*)d_in[1];
    const float* weight   = (const float*)d_in[2];

    static int smem_set = 0;
    if (!smem_set) {
        cudaFuncSetAttribute(k_gemm_loss, cudaFuncAttributeMaxDynamicSharedMemorySize,
                             DSMEM_BYTES);
        smem_set = 1;
    }

    k_pre<<<4096, 256>>>(weight, latent);
    k_gemm_loss<<<dim3(GX, GY), 256, DSMEM_BYTES>>>(true_sum, (float*)d_out, out_size);
}